// round 6
// baseline (speedup 1.0000x reference)
#include <cuda_runtime.h>
#include <math.h>

#define TCNT 4
#define CH 3
#define HH 128
#define WW 128
#define PSZ 5
#define KSEL 14
#define WSZ 29
#define WHALF 14
#define PADT 16
#define XPH 160
#define XPW 160
#define TX 32
#define TY 8
#define NOFF (WSZ*WSZ)
#define NGRP ((NOFF + 3) / 4)     /* 211 groups of 4 offsets */
#define DFEAT 75
#define PLANE (TCNT*HH*WW)

typedef unsigned long long u64;

// ---------------- device scratch (no allocations allowed) ----------------
__device__ float  g_mean[TCNT*CH];
__device__ float  g_beta;
__device__ float4 g_xp[TCNT*XPH*XPW];          // normalized, mean-sub, reflect-padded; c in .x/.y/.z
__device__ float  g_pdeno[DFEAT*PLANE];        // plane-major [d][t][H][W]
__device__ __align__(8) unsigned short g_ord[NGRP*4];  // ring-ordered offsets: (oy<<5)|ox

__device__ __forceinline__ u64 f2add(u64 a, u64 b) {
    u64 r; asm("add.rn.f32x2 %0,%1,%2;" : "=l"(r) : "l"(a), "l"(b)); return r;
}
__device__ __forceinline__ u64 packf2(float x, float y) {
    return ((u64)__float_as_uint(y) << 32) | (u64)__float_as_uint(x);
}

// ---------------- per (t,c) mean + beta ----------------
__global__ void k_means(const float* __restrict__ noisy, const int* __restrict__ sigp) {
    if (blockIdx.x == 0 && threadIdx.x == 0) {
        unsigned bits = *(const unsigned*)sigp;
        float sv = (bits >> 23) ? __uint_as_float(bits) : (float)(int)bits;
        float sig = sv / 127.5f;
        g_beta = 1.0f / (2.0f * sig * sig * (float)DFEAT);
    }
    int b = blockIdx.x;   // t*3+c
    const float* p = noisy + (size_t)b * (HH*WW);
    float s = 0.f;
    for (int i = threadIdx.x; i < HH*WW; i += 256) s += p[i];
    __shared__ float sm[8];
    #pragma unroll
    for (int off = 16; off; off >>= 1) s += __shfl_down_sync(0xffffffffu, s, off);
    if ((threadIdx.x & 31) == 0) sm[threadIdx.x >> 5] = s;
    __syncthreads();
    if (threadIdx.x == 0) {
        float tot = 0.f;
        #pragma unroll
        for (int i = 0; i < 8; i++) tot += sm[i];
        g_mean[b] = tot * (1.0f/(HH*WW)) * (1.0f/127.5f) - 1.0f;
    }
}

// ---------------- build padded normalized image (float4 per pixel) ----------------
__global__ void k_xp(const float* __restrict__ noisy) {
    int idx = blockIdx.x * 256 + threadIdx.x;       // over t*XPH*XPW
    if (idx >= TCNT*XPH*XPW) return;
    int ix = idx % XPW;
    int r  = idx / XPW;
    int iy = r % XPH;
    int t  = r / XPH;
    int jy = iy - PADT; jy = jy < 0 ? -jy : (jy > HH-1 ? 2*(HH-1)-jy : jy);
    int jx = ix - PADT; jx = jx < 0 ? -jx : (jx > WW-1 ? 2*(WW-1)-jx : jx);
    const float* base = noisy + (size_t)t * CH * HH * WW;
    float4 v;
    v.x = base[(size_t)(0*HH+jy)*WW + jx] * (1.f/127.5f) - 1.f - g_mean[t*3+0];
    v.y = base[(size_t)(1*HH+jy)*WW + jx] * (1.f/127.5f) - 1.f - g_mean[t*3+1];
    v.z = base[(size_t)(2*HH+jy)*WW + jx] * (1.f/127.5f) - 1.f - g_mean[t*3+2];
    v.w = 0.f;
    g_xp[idx] = v;
}

// ---------------- ring-order the 841 offsets (center outward) ----------------
__global__ void k_ord() {
    int o = blockIdx.x * blockDim.x + threadIdx.x;
    if (o >= NOFF) return;
    int oy = o / WSZ, ox = o - (o/WSZ)*WSZ;
    int dy = oy - WHALF, dx = ox - WHALF;
    int ady = dy < 0 ? -dy : dy, adx = dx < 0 ? -dx : dx;
    int rr = ady > adx ? ady : adx;
    int before = (rr == 0) ? 0 : (2*rr-1)*(2*rr-1);
    int cnt = 0;
    for (int yy = WHALF - rr; yy < oy; yy++) {
        int a = yy - WHALF; a = a < 0 ? -a : a;
        cnt += (a == rr) ? (2*rr + 1) : 2;
    }
    if (ady == rr) cnt += dx + rr;            // full row: columns before ox
    else          cnt += (dx == rr) ? 1 : 0;  // partial row: only +/- rr columns
    g_ord[before + cnt] = (unsigned short)((oy << 5) | ox);
}

// decode packed (oy<<5)|ox -> (off_lin<<16) | raster
__device__ __forceinline__ unsigned decode_off(unsigned s) {
    unsigned oy = s >> 5, ox = s & 31u;
    return ((oy * 64u + ox) << 16) | (oy * (unsigned)WSZ + ox);
}

// ---------------- main: distances + top-K + softmax + patch gather ----------------
__global__ void __launch_bounds__(256, 2) k_main() {
    __shared__ float4 reg4[40*64];        // 40KB region
    __shared__ u64    e_sm[4][12*36];     // 2 sides x 2 planes (each plane = 2 offsets packed f32x2)
    __shared__ u64    hbuf[2][8][36];     // per-chain, per-warp horizontal row buffers

    int t   = blockIdx.z;
    int ty0 = blockIdx.y * TY;
    int tx0 = blockIdx.x * TX;
    int tid = threadIdx.x;

    // stage region
    const float4* xp = g_xp + (size_t)t * XPH * XPW;
    #pragma unroll
    for (int i = tid; i < 40*64; i += 256) {
        int r = i >> 6, c = i & 63;
        reg4[i] = xp[(size_t)(ty0 + r) * XPW + tx0 + c];
    }
    __syncthreads();

    // register-cached query pixels for the e-plane (slots tid and tid+256)
    int er1 = tid / 36, ec1 = tid - er1 * 36;
    int it2 = tid + 256;
    int er2 = it2 / 36, ec2 = it2 - er2 * 36;       // valid when tid < 176
    float4 q1 = reg4[(er1 + 14) * 64 + (ec1 + 14)];
    float4 q2 = (tid < 176) ? reg4[(er2 + 14) * 64 + (ec2 + 14)] : make_float4(0.f,0.f,0.f,0.f);
    int nb1 = er1 * 64 + ec1;
    int nb2 = er2 * 64 + ec2;

    int ly = tid >> 5, l = tid & 31;

    unsigned keys[KSEL];
    #pragma unroll
    for (int i = 0; i < KSEL; i++) keys[i] = 0xFFFFFFFFu;

    // fill two f32x2 planes (4 offsets) from group word gw
    auto fillG = [&](u64* pA, u64* pB, u64 gw) {
        unsigned w0 = decode_off((unsigned)(gw       ) & 0xFFFFu);
        unsigned w1 = decode_off((unsigned)(gw >> 16 ) & 0xFFFFu);
        unsigned w2 = decode_off((unsigned)(gw >> 32 ) & 0xFFFFu);
        unsigned w3 = decode_off((unsigned)(gw >> 48 ) & 0xFFFFu);
        int o0 = (int)(w0 >> 16), o1 = (int)(w1 >> 16);
        int o2 = (int)(w2 >> 16), o3 = (int)(w3 >> 16);
        {
            float4 n0 = reg4[nb1 + o0], n1 = reg4[nb1 + o1];
            float4 n2 = reg4[nb1 + o2], n3 = reg4[nb1 + o3];
            float a0 = q1.x-n0.x, b0 = q1.y-n0.y, c0 = q1.z-n0.z;
            float a1 = q1.x-n1.x, b1 = q1.y-n1.y, c1 = q1.z-n1.z;
            float a2 = q1.x-n2.x, b2 = q1.y-n2.y, c2 = q1.z-n2.z;
            float a3 = q1.x-n3.x, b3 = q1.y-n3.y, c3 = q1.z-n3.z;
            pA[tid] = packf2(a0*a0 + b0*b0 + c0*c0, a1*a1 + b1*b1 + c1*c1);
            pB[tid] = packf2(a2*a2 + b2*b2 + c2*c2, a3*a3 + b3*b3 + c3*c3);
        }
        if (tid < 176) {
            float4 n0 = reg4[nb2 + o0], n1 = reg4[nb2 + o1];
            float4 n2 = reg4[nb2 + o2], n3 = reg4[nb2 + o3];
            float a0 = q2.x-n0.x, b0 = q2.y-n0.y, c0 = q2.z-n0.z;
            float a1 = q2.x-n1.x, b1 = q2.y-n1.y, c1 = q2.z-n1.z;
            float a2 = q2.x-n2.x, b2 = q2.y-n2.y, c2 = q2.z-n2.z;
            float a3 = q2.x-n3.x, b3 = q2.y-n3.y, c3 = q2.z-n3.z;
            pA[it2] = packf2(a0*a0 + b0*b0 + c0*c0, a1*a1 + b1*b1 + c1*c1);
            pB[it2] = packf2(a2*a2 + b2*b2 + c2*c2, a3*a3 + b3*b3 + c3*c3);
        }
    };

    // reduce 4 offsets (two independent chains) + top-K insert
    auto bcG = [&](const u64* pA, const u64* pB, u64 gw, bool kill123) {
        const u64* rA = pA + ly * 36;
        const u64* rB = pB + ly * 36;
        int c2 = 32 + (l & 3);
        u64 vaA = f2add(f2add(f2add(rA[l], rA[36+l]), f2add(rA[72+l], rA[108+l])), rA[144+l]);
        u64 vaB = f2add(f2add(f2add(rB[l], rB[36+l]), f2add(rB[72+l], rB[108+l])), rB[144+l]);
        u64 vbA = f2add(f2add(f2add(rA[c2], rA[36+c2]), f2add(rA[72+c2], rA[108+c2])), rA[144+c2]);
        u64 vbB = f2add(f2add(f2add(rB[c2], rB[36+c2]), f2add(rB[72+c2], rB[108+c2])), rB[144+c2]);
        u64* hA = hbuf[0][ly];
        u64* hB = hbuf[1][ly];
        hA[l] = vaA;
        hB[l] = vaB;
        if (l < 4) { hA[32 + l] = vbA; hB[32 + l] = vbB; }
        __syncwarp(0xffffffffu);
        u64 dA = f2add(f2add(f2add(hA[l], hA[l+1]), f2add(hA[l+2], hA[l+3])), hA[l+4]);
        u64 dB = f2add(f2add(f2add(hB[l], hB[l+1]), f2add(hB[l+2], hB[l+3])), hB[l+4]);
        unsigned r0 = decode_off((unsigned)(gw       ) & 0xFFFFu) & 0x3FFu;
        unsigned r1 = decode_off((unsigned)(gw >> 16 ) & 0xFFFFu) & 0x3FFu;
        unsigned r2 = decode_off((unsigned)(gw >> 32 ) & 0xFFFFu) & 0x3FFu;
        unsigned r3 = decode_off((unsigned)(gw >> 48 ) & 0xFFFFu) & 0x3FFu;
        unsigned k0 = ((unsigned)dA         & 0xFFFFFC00u) | r0;
        unsigned k1 = ((unsigned)(dA >> 32) & 0xFFFFFC00u) | r1;
        unsigned k2 = ((unsigned)dB         & 0xFFFFFC00u) | r2;
        unsigned k3 = ((unsigned)(dB >> 32) & 0xFFFFFC00u) | r3;
        if (kill123) { k1 = 0xFFFFFFFFu; k2 = 0xFFFFFFFFu; k3 = 0xFFFFFFFFu; }
        unsigned mn = umin(umin(k0, k1), umin(k2, k3));
        if (__any_sync(0xffffffffu, mn < keys[KSEL-1])) {
            #pragma unroll
            for (int s = KSEL-1; s >= 1; s--) keys[s] = umin(keys[s], umax(keys[s-1], k0));
            keys[0] = umin(keys[0], k0);
            #pragma unroll
            for (int s = KSEL-1; s >= 1; s--) keys[s] = umin(keys[s], umax(keys[s-1], k1));
            keys[0] = umin(keys[0], k1);
            #pragma unroll
            for (int s = KSEL-1; s >= 1; s--) keys[s] = umin(keys[s], umax(keys[s-1], k2));
            keys[0] = umin(keys[0], k2);
            #pragma unroll
            for (int s = KSEL-1; s >= 1; s--) keys[s] = umin(keys[s], umax(keys[s-1], k3));
            keys[0] = umin(keys[0], k3);
        }
    };

    // sanitize group word: last group has 1 real offset, replicate it
    auto sanitize = [](u64 gw, int g) -> u64 {
        if (g == NGRP - 1) {
            u64 s0 = gw & 0xFFFFu;
            gw = s0 | (s0 << 16) | (s0 << 32) | (s0 << 48);
        }
        return gw;
    };

    const u64* ordp = (const u64*)g_ord;
    u64 w_cur = sanitize(ordp[0], 0);
    fillG(e_sm[0], e_sm[1], w_cur);
    u64 w_nxt = (NGRP > 1) ? sanitize(ordp[1], 1) : 0;

    int side = 0;
    for (int g = 0; g < NGRP; g++) {
        __syncthreads();
        if (g + 1 < NGRP) {
            int s2 = (side ^ 1) << 1;
            fillG(e_sm[s2], e_sm[s2 | 1], w_nxt);
        }
        u64 w_n2 = (g + 2 < NGRP) ? sanitize(ordp[g + 2], g + 2) : 0;
        int sc = side << 1;
        bcG(e_sm[sc], e_sm[sc | 1], w_cur, g == NGRP - 1);
        w_cur = w_nxt; w_nxt = w_n2;
        side ^= 1;
    }

    // --- softmax over (quantized) distances ---
    float w[KSEL];
    int   olin[KSEL];
    float beta = g_beta;
    float d0 = __uint_as_float(keys[0] & 0xFFFFFC00u);
    float ssum = 0.f;
    #pragma unroll
    for (int i = 0; i < KSEL; i++) {
        float di = __uint_as_float(keys[i] & 0xFFFFFC00u);
        float wi = expf(beta * (d0 - di));
        w[i] = wi; ssum += wi;
        int o  = (int)(keys[i] & 0x3FFu);
        int oyk = o / WSZ;
        int oxk = o - oyk * WSZ;
        olin[i] = oyk * 64 + oxk;
    }
    float inv = 1.0f / ssum;
    #pragma unroll
    for (int i = 0; i < KSEL; i++) w[i] *= inv;

    // --- weighted patch gather from smem region, plane-major write ---
    float* pd = g_pdeno + ((size_t)t * HH + (ty0 + ly)) * WW + (tx0 + l);
    int base_px = ly * 64 + l;
    #pragma unroll
    for (int dy = 0; dy < PSZ; dy++) {
        #pragma unroll
        for (int dx = 0; dx < PSZ; dx++) {
            float ax = 0.f, ay = 0.f, az = 0.f;
            int bb = base_px + dy * 64 + dx;
            #pragma unroll
            for (int k = 0; k < KSEL; k++) {
                float4 v = reg4[bb + olin[k]];
                ax += w[k] * v.x;
                ay += w[k] * v.y;
                az += w[k] * v.z;
            }
            int p = (dy * PSZ + dx) * 3;
            pd[(size_t)(p + 0) * PLANE] = ax;
            pd[(size_t)(p + 1) * PLANE] = ay;
            pd[(size_t)(p + 2) * PLANE] = az;
        }
    }
}

// ---------------- fold + denormalize ----------------
__global__ void k_fold(float* __restrict__ out) {
    int idx = blockIdx.x * 256 + threadIdx.x;        // over t*c*H*W
    if (idx >= TCNT*CH*HH*WW) return;
    int x = idx & 127;
    int r = idx >> 7;
    int y = r & 127;
    r >>= 7;
    int c = r % 3;
    int t = r / 3;
    float s = 0.f;
    int n = 0;
    #pragma unroll
    for (int py = 0; py < PSZ; py++) {
        int yy = y + 2 - py;
        if (yy < 0 || yy > HH-1) continue;
        #pragma unroll
        for (int px = 0; px < PSZ; px++) {
            int xx = x + 2 - px;
            if (xx < 0 || xx > WW-1) continue;
            int p = (py * PSZ + px) * 3 + c;
            s += g_pdeno[(size_t)p * PLANE + ((size_t)t * HH + yy) * WW + xx];
            n++;
        }
    }
    out[idx] = 127.5f * (s / (float)n + g_mean[t*3+c] + 1.0f);
}

// ---------------- launch ----------------
extern "C" void kernel_launch(void* const* d_in, const int* in_sizes, int n_in,
                              void* d_out, int out_size) {
    const float* noisy = (const float*)d_in[0];
    const int*   sigp  = (const int*)d_in[1];
    float*       out   = (float*)d_out;

    k_means<<<TCNT*CH, 256>>>(noisy, sigp);
    k_xp<<<(TCNT*XPH*XPW + 255)/256, 256>>>(noisy);
    k_ord<<<(NOFF + 255)/256, 256>>>();
    dim3 grid(WW/TX, HH/TY, TCNT);
    k_main<<<grid, 256>>>();
    k_fold<<<(TCNT*CH*HH*WW + 255)/256, 256>>>(out);
}

// round 7
// speedup vs baseline: 1.2174x; 1.2174x over previous
#include <cuda_runtime.h>
#include <math.h>

#define TCNT 4
#define CH 3
#define HH 128
#define WW 128
#define PSZ 5
#define KSEL 14
#define WSZ 29
#define WHALF 14
#define PADT 16
#define XPH 160
#define XPW 160
#define TX 32
#define TY 8
#define NOFF (WSZ*WSZ)
#define NGRP ((NOFF + 3) / 4)     /* 211 groups of 4 offsets */
#define DFEAT 75
#define PLANE (TCNT*HH*WW)

typedef unsigned long long u64;

// ---------------- device scratch (no allocations allowed) ----------------
__device__ float  g_mean[TCNT*CH];
__device__ float  g_beta;
__device__ float4 g_xp[TCNT*XPH*XPW];          // normalized, mean-sub, reflect-padded; c in .x/.y/.z
__device__ float  g_pdeno[DFEAT*PLANE];        // plane-major [d][t][H][W]
__device__ __align__(16) unsigned g_ordw[NGRP*4];  // ring-ordered, pre-decoded: (off_lin<<16)|raster

__device__ __forceinline__ u64 f2add(u64 a, u64 b) {
    u64 r; asm("add.rn.f32x2 %0,%1,%2;" : "=l"(r) : "l"(a), "l"(b)); return r;
}
__device__ __forceinline__ u64 packf2(float x, float y) {
    return ((u64)__float_as_uint(y) << 32) | (u64)__float_as_uint(x);
}

// ---------------- per (t,c) mean + beta ----------------
__global__ void k_means(const float* __restrict__ noisy, const int* __restrict__ sigp) {
    if (blockIdx.x == 0 && threadIdx.x == 0) {
        unsigned bits = *(const unsigned*)sigp;
        float sv = (bits >> 23) ? __uint_as_float(bits) : (float)(int)bits;
        float sig = sv / 127.5f;
        g_beta = 1.0f / (2.0f * sig * sig * (float)DFEAT);
    }
    int b = blockIdx.x;   // t*3+c
    const float* p = noisy + (size_t)b * (HH*WW);
    float s = 0.f;
    for (int i = threadIdx.x; i < HH*WW; i += 256) s += p[i];
    __shared__ float sm[8];
    #pragma unroll
    for (int off = 16; off; off >>= 1) s += __shfl_down_sync(0xffffffffu, s, off);
    if ((threadIdx.x & 31) == 0) sm[threadIdx.x >> 5] = s;
    __syncthreads();
    if (threadIdx.x == 0) {
        float tot = 0.f;
        #pragma unroll
        for (int i = 0; i < 8; i++) tot += sm[i];
        g_mean[b] = tot * (1.0f/(HH*WW)) * (1.0f/127.5f) - 1.0f;
    }
}

// ---------------- build padded normalized image (float4 per pixel) ----------------
__global__ void k_xp(const float* __restrict__ noisy) {
    int idx = blockIdx.x * 256 + threadIdx.x;       // over t*XPH*XPW
    if (idx >= TCNT*XPH*XPW) return;
    int ix = idx % XPW;
    int r  = idx / XPW;
    int iy = r % XPH;
    int t  = r / XPH;
    int jy = iy - PADT; jy = jy < 0 ? -jy : (jy > HH-1 ? 2*(HH-1)-jy : jy);
    int jx = ix - PADT; jx = jx < 0 ? -jx : (jx > WW-1 ? 2*(WW-1)-jx : jx);
    const float* base = noisy + (size_t)t * CH * HH * WW;
    float4 v;
    v.x = base[(size_t)(0*HH+jy)*WW + jx] * (1.f/127.5f) - 1.f - g_mean[t*3+0];
    v.y = base[(size_t)(1*HH+jy)*WW + jx] * (1.f/127.5f) - 1.f - g_mean[t*3+1];
    v.z = base[(size_t)(2*HH+jy)*WW + jx] * (1.f/127.5f) - 1.f - g_mean[t*3+2];
    v.w = 0.f;
    g_xp[idx] = v;
}

// ---------------- ring-order the 841 offsets (center outward), pre-decoded ----------------
__global__ void k_ord() {
    int o = blockIdx.x * blockDim.x + threadIdx.x;
    if (o >= NOFF) return;
    int oy = o / WSZ, ox = o - (o/WSZ)*WSZ;
    int dy = oy - WHALF, dx = ox - WHALF;
    int ady = dy < 0 ? -dy : dy, adx = dx < 0 ? -dx : dx;
    int rr = ady > adx ? ady : adx;
    int before = (rr == 0) ? 0 : (2*rr-1)*(2*rr-1);
    int cnt = 0;
    for (int yy = WHALF - rr; yy < oy; yy++) {
        int a = yy - WHALF; a = a < 0 ? -a : a;
        cnt += (a == rr) ? (2*rr + 1) : 2;
    }
    if (ady == rr) cnt += dx + rr;            // full row: columns before ox
    else          cnt += (dx == rr) ? 1 : 0;  // partial row: only +/- rr columns
    g_ordw[before + cnt] = (((unsigned)oy * 64u + (unsigned)ox) << 16)
                         | ((unsigned)oy * (unsigned)WSZ + (unsigned)ox);
}

// ---------------- main: distances + top-K + softmax + patch gather ----------------
__global__ void __launch_bounds__(256, 3) k_main() {
    __shared__ float4 reg4[40*64];        // 40KB region
    __shared__ u64    e_sm[4][12*36];     // 2 sides x 2 planes (each plane = 2 offsets packed f32x2)
    __shared__ u64    hbuf[2][8][36];     // per-chain, per-warp horizontal row buffers

    int t   = blockIdx.z;
    int ty0 = blockIdx.y * TY;
    int tx0 = blockIdx.x * TX;
    int tid = threadIdx.x;

    // stage region
    const float4* xp = g_xp + (size_t)t * XPH * XPW;
    #pragma unroll
    for (int i = tid; i < 40*64; i += 256) {
        int r = i >> 6, c = i & 63;
        reg4[i] = xp[(size_t)(ty0 + r) * XPW + tx0 + c];
    }
    __syncthreads();

    // register-cached query pixels for the e-plane (slots tid and tid+256)
    int er1 = tid / 36, ec1 = tid - er1 * 36;
    int it2 = tid + 256;
    int er2 = it2 / 36, ec2 = it2 - er2 * 36;       // valid when tid < 176
    float4 q1 = reg4[(er1 + 14) * 64 + (ec1 + 14)];
    float4 q2 = (tid < 176) ? reg4[(er2 + 14) * 64 + (ec2 + 14)] : make_float4(0.f,0.f,0.f,0.f);
    int nb1 = er1 * 64 + ec1;
    int nb2 = er2 * 64 + ec2;

    int ly = tid >> 5, l = tid & 31;

    unsigned keys[KSEL];
    #pragma unroll
    for (int i = 0; i < KSEL; i++) keys[i] = 0xFFFFFFFFu;

    // fill two f32x2 planes (4 offsets) from pre-decoded group word
    auto fillG = [&](u64* pA, u64* pB, uint4 gw) {
        int o0 = (int)(gw.x >> 16), o1 = (int)(gw.y >> 16);
        int o2 = (int)(gw.z >> 16), o3 = (int)(gw.w >> 16);
        {
            float4 n0 = reg4[nb1 + o0], n1 = reg4[nb1 + o1];
            float4 n2 = reg4[nb1 + o2], n3 = reg4[nb1 + o3];
            float a0 = q1.x-n0.x, b0 = q1.y-n0.y, c0 = q1.z-n0.z;
            float a1 = q1.x-n1.x, b1 = q1.y-n1.y, c1 = q1.z-n1.z;
            float a2 = q1.x-n2.x, b2 = q1.y-n2.y, c2 = q1.z-n2.z;
            float a3 = q1.x-n3.x, b3 = q1.y-n3.y, c3 = q1.z-n3.z;
            pA[tid] = packf2(a0*a0 + b0*b0 + c0*c0, a1*a1 + b1*b1 + c1*c1);
            pB[tid] = packf2(a2*a2 + b2*b2 + c2*c2, a3*a3 + b3*b3 + c3*c3);
        }
        if (tid < 176) {
            float4 n0 = reg4[nb2 + o0], n1 = reg4[nb2 + o1];
            float4 n2 = reg4[nb2 + o2], n3 = reg4[nb2 + o3];
            float a0 = q2.x-n0.x, b0 = q2.y-n0.y, c0 = q2.z-n0.z;
            float a1 = q2.x-n1.x, b1 = q2.y-n1.y, c1 = q2.z-n1.z;
            float a2 = q2.x-n2.x, b2 = q2.y-n2.y, c2 = q2.z-n2.z;
            float a3 = q2.x-n3.x, b3 = q2.y-n3.y, c3 = q2.z-n3.z;
            pA[it2] = packf2(a0*a0 + b0*b0 + c0*c0, a1*a1 + b1*b1 + c1*c1);
            pB[it2] = packf2(a2*a2 + b2*b2 + c2*c2, a3*a3 + b3*b3 + c3*c3);
        }
    };

    // single-key guarded insert (cheap VOTE; network only when some lane inserts)
    auto ins1 = [&](unsigned k) {
        if (__any_sync(0xffffffffu, k < keys[KSEL-1])) {
            #pragma unroll
            for (int s = KSEL-1; s >= 1; s--) keys[s] = umin(keys[s], umax(keys[s-1], k));
            keys[0] = umin(keys[0], k);
        }
    };

    // reduce 4 offsets (two independent chains) + top-K inserts
    auto bcG = [&](const u64* pA, const u64* pB, uint4 gw, bool kill123) {
        const u64* rA = pA + ly * 36;
        const u64* rB = pB + ly * 36;
        int c2 = 32 + (l & 3);
        u64 vaA = f2add(f2add(f2add(rA[l], rA[36+l]), f2add(rA[72+l], rA[108+l])), rA[144+l]);
        u64 vaB = f2add(f2add(f2add(rB[l], rB[36+l]), f2add(rB[72+l], rB[108+l])), rB[144+l]);
        u64 vbA = f2add(f2add(f2add(rA[c2], rA[36+c2]), f2add(rA[72+c2], rA[108+c2])), rA[144+c2]);
        u64 vbB = f2add(f2add(f2add(rB[c2], rB[36+c2]), f2add(rB[72+c2], rB[108+c2])), rB[144+c2]);
        u64* hA = hbuf[0][ly];
        u64* hB = hbuf[1][ly];
        hA[l] = vaA;
        hB[l] = vaB;
        if (l < 4) { hA[32 + l] = vbA; hB[32 + l] = vbB; }
        __syncwarp(0xffffffffu);
        u64 dA = f2add(f2add(f2add(hA[l], hA[l+1]), f2add(hA[l+2], hA[l+3])), hA[l+4]);
        u64 dB = f2add(f2add(f2add(hB[l], hB[l+1]), f2add(hB[l+2], hB[l+3])), hB[l+4]);
        unsigned k0 = ((unsigned)dA         & 0xFFFFFC00u) | (gw.x & 0x3FFu);
        unsigned k1 = ((unsigned)(dA >> 32) & 0xFFFFFC00u) | (gw.y & 0x3FFu);
        unsigned k2 = ((unsigned)dB         & 0xFFFFFC00u) | (gw.z & 0x3FFu);
        unsigned k3 = ((unsigned)(dB >> 32) & 0xFFFFFC00u) | (gw.w & 0x3FFu);
        if (kill123) { k1 = 0xFFFFFFFFu; k2 = 0xFFFFFFFFu; k3 = 0xFFFFFFFFu; }
        ins1(k0); ins1(k1); ins1(k2); ins1(k3);
    };

    const uint4* ordp = (const uint4*)g_ordw;
    auto loadg = [&](int g) -> uint4 {
        uint4 v = ordp[g];
        if (g == NGRP - 1) { v.y = v.x; v.z = v.x; v.w = v.x; }  // last group: 1 real offset
        return v;
    };

    uint4 w_cur = loadg(0);
    fillG(e_sm[0], e_sm[1], w_cur);
    uint4 w_nxt = loadg(1);

    #pragma unroll 2
    for (int g = 0; g < NGRP; g++) {
        int side = g & 1;
        __syncthreads();
        if (g + 1 < NGRP) {
            int s2 = (side ^ 1) << 1;
            fillG(e_sm[s2], e_sm[s2 | 1], w_nxt);
        }
        uint4 w_n2 = (g + 2 < NGRP) ? loadg(g + 2) : make_uint4(0,0,0,0);
        int sc = side << 1;
        bcG(e_sm[sc], e_sm[sc | 1], w_cur, g == NGRP - 1);
        w_cur = w_nxt; w_nxt = w_n2;
    }

    // --- softmax over (quantized) distances ---
    float w[KSEL];
    int   olin[KSEL];
    float beta = g_beta;
    float d0 = __uint_as_float(keys[0] & 0xFFFFFC00u);
    float ssum = 0.f;
    #pragma unroll
    for (int i = 0; i < KSEL; i++) {
        float di = __uint_as_float(keys[i] & 0xFFFFFC00u);
        float wi = expf(beta * (d0 - di));
        w[i] = wi; ssum += wi;
        int o  = (int)(keys[i] & 0x3FFu);
        int oyk = o / WSZ;
        int oxk = o - oyk * WSZ;
        olin[i] = oyk * 64 + oxk;
    }
    float inv = 1.0f / ssum;
    #pragma unroll
    for (int i = 0; i < KSEL; i++) w[i] *= inv;

    // --- weighted patch gather from smem region, plane-major write ---
    float* pd = g_pdeno + ((size_t)t * HH + (ty0 + ly)) * WW + (tx0 + l);
    int base_px = ly * 64 + l;
    #pragma unroll
    for (int dy = 0; dy < PSZ; dy++) {
        #pragma unroll
        for (int dx = 0; dx < PSZ; dx++) {
            float ax = 0.f, ay = 0.f, az = 0.f;
            int bb = base_px + dy * 64 + dx;
            #pragma unroll
            for (int k = 0; k < KSEL; k++) {
                float4 v = reg4[bb + olin[k]];
                ax += w[k] * v.x;
                ay += w[k] * v.y;
                az += w[k] * v.z;
            }
            int p = (dy * PSZ + dx) * 3;
            pd[(size_t)(p + 0) * PLANE] = ax;
            pd[(size_t)(p + 1) * PLANE] = ay;
            pd[(size_t)(p + 2) * PLANE] = az;
        }
    }
}

// ---------------- fold + denormalize ----------------
__global__ void k_fold(float* __restrict__ out) {
    int idx = blockIdx.x * 256 + threadIdx.x;        // over t*c*H*W
    if (idx >= TCNT*CH*HH*WW) return;
    int x = idx & 127;
    int r = idx >> 7;
    int y = r & 127;
    r >>= 7;
    int c = r % 3;
    int t = r / 3;
    float s = 0.f;
    int n = 0;
    #pragma unroll
    for (int py = 0; py < PSZ; py++) {
        int yy = y + 2 - py;
        if (yy < 0 || yy > HH-1) continue;
        #pragma unroll
        for (int px = 0; px < PSZ; px++) {
            int xx = x + 2 - px;
            if (xx < 0 || xx > WW-1) continue;
            int p = (py * PSZ + px) * 3 + c;
            s += g_pdeno[(size_t)p * PLANE + ((size_t)t * HH + yy) * WW + xx];
            n++;
        }
    }
    out[idx] = 127.5f * (s / (float)n + g_mean[t*3+c] + 1.0f);
}

// ---------------- launch ----------------
extern "C" void kernel_launch(void* const* d_in, const int* in_sizes, int n_in,
                              void* d_out, int out_size) {
    const float* noisy = (const float*)d_in[0];
    const int*   sigp  = (const int*)d_in[1];
    float*       out   = (float*)d_out;

    k_means<<<TCNT*CH, 256>>>(noisy, sigp);
    k_xp<<<(TCNT*XPH*XPW + 255)/256, 256>>>(noisy);
    k_ord<<<(NOFF + 255)/256, 256>>>();
    dim3 grid(WW/TX, HH/TY, TCNT);
    k_main<<<grid, 256>>>();
    k_fold<<<(TCNT*CH*HH*WW + 255)/256, 256>>>(out);
}

// round 8
// speedup vs baseline: 1.2650x; 1.0391x over previous
#include <cuda_runtime.h>
#include <math.h>

#define TCNT 4
#define CH 3
#define HH 128
#define WW 128
#define PSZ 5
#define KSEL 14
#define WSZ 29
#define WHALF 14
#define PADT 16
#define XPH 160
#define XPW 160
#define TX 32
#define TY 8
#define NOFF (WSZ*WSZ)
#define NGRP ((NOFF + 3) / 4)     /* 211 groups of 4 offsets */
#define DFEAT 75
#define PLANE (TCNT*HH*WW)

// dynamic smem layout (bytes)
#define SM_REG4   0                      /* float4[40*64]  = 40960 */
#define SM_E      40960                  /* u64[4][432]    = 13824 */
#define SM_H      (40960 + 13824)        /* u64[2][8][36]  = 4608  */
#define SM_TOTAL  (40960 + 13824 + 4608) /* 59392 */

typedef unsigned long long u64;

// ---------------- device scratch (no allocations allowed) ----------------
__device__ float  g_mean[TCNT*CH];
__device__ float  g_beta;
__device__ float4 g_xp[TCNT*XPH*XPW];          // normalized, mean-sub, reflect-padded; c in .x/.y/.z
__device__ float  g_pdeno[DFEAT*PLANE];        // plane-major [d][t][H][W]
__device__ __align__(16) unsigned g_ordw[NGRP*4];  // ring-ordered, pre-decoded: (off_lin<<16)|raster

__device__ __forceinline__ u64 f2add(u64 a, u64 b) {
    u64 r; asm("add.rn.f32x2 %0,%1,%2;" : "=l"(r) : "l"(a), "l"(b)); return r;
}
__device__ __forceinline__ u64 packf2(float x, float y) {
    return ((u64)__float_as_uint(y) << 32) | (u64)__float_as_uint(x);
}

// ---------------- per (t,c) mean + beta ----------------
__global__ void k_means(const float* __restrict__ noisy, const int* __restrict__ sigp) {
    if (blockIdx.x == 0 && threadIdx.x == 0) {
        unsigned bits = *(const unsigned*)sigp;
        float sv = (bits >> 23) ? __uint_as_float(bits) : (float)(int)bits;
        float sig = sv / 127.5f;
        g_beta = 1.0f / (2.0f * sig * sig * (float)DFEAT);
    }
    int b = blockIdx.x;   // t*3+c
    const float* p = noisy + (size_t)b * (HH*WW);
    float s = 0.f;
    for (int i = threadIdx.x; i < HH*WW; i += 256) s += p[i];
    __shared__ float sm[8];
    #pragma unroll
    for (int off = 16; off; off >>= 1) s += __shfl_down_sync(0xffffffffu, s, off);
    if ((threadIdx.x & 31) == 0) sm[threadIdx.x >> 5] = s;
    __syncthreads();
    if (threadIdx.x == 0) {
        float tot = 0.f;
        #pragma unroll
        for (int i = 0; i < 8; i++) tot += sm[i];
        g_mean[b] = tot * (1.0f/(HH*WW)) * (1.0f/127.5f) - 1.0f;
    }
}

// ---------------- build padded normalized image (float4 per pixel) ----------------
__global__ void k_xp(const float* __restrict__ noisy) {
    int idx = blockIdx.x * 256 + threadIdx.x;       // over t*XPH*XPW
    if (idx >= TCNT*XPH*XPW) return;
    int ix = idx % XPW;
    int r  = idx / XPW;
    int iy = r % XPH;
    int t  = r / XPH;
    int jy = iy - PADT; jy = jy < 0 ? -jy : (jy > HH-1 ? 2*(HH-1)-jy : jy);
    int jx = ix - PADT; jx = jx < 0 ? -jx : (jx > WW-1 ? 2*(WW-1)-jx : jx);
    const float* base = noisy + (size_t)t * CH * HH * WW;
    float4 v;
    v.x = base[(size_t)(0*HH+jy)*WW + jx] * (1.f/127.5f) - 1.f - g_mean[t*3+0];
    v.y = base[(size_t)(1*HH+jy)*WW + jx] * (1.f/127.5f) - 1.f - g_mean[t*3+1];
    v.z = base[(size_t)(2*HH+jy)*WW + jx] * (1.f/127.5f) - 1.f - g_mean[t*3+2];
    v.w = 0.f;
    g_xp[idx] = v;
}

// ---------------- ring-order the 841 offsets (center outward), pre-decoded ----------------
__global__ void k_ord() {
    int o = blockIdx.x * blockDim.x + threadIdx.x;
    if (o >= NOFF) return;
    int oy = o / WSZ, ox = o - (o/WSZ)*WSZ;
    int dy = oy - WHALF, dx = ox - WHALF;
    int ady = dy < 0 ? -dy : dy, adx = dx < 0 ? -dx : dx;
    int rr = ady > adx ? ady : adx;
    int before = (rr == 0) ? 0 : (2*rr-1)*(2*rr-1);
    int cnt = 0;
    for (int yy = WHALF - rr; yy < oy; yy++) {
        int a = yy - WHALF; a = a < 0 ? -a : a;
        cnt += (a == rr) ? (2*rr + 1) : 2;
    }
    if (ady == rr) cnt += dx + rr;            // full row: columns before ox
    else          cnt += (dx == rr) ? 1 : 0;  // partial row: only +/- rr columns
    g_ordw[before + cnt] = (((unsigned)oy * 64u + (unsigned)ox) << 16)
                         | ((unsigned)oy * (unsigned)WSZ + (unsigned)ox);
}

// ---------------- main: distances + top-K + softmax + patch gather ----------------
__global__ void __launch_bounds__(256, 3) k_main() {
    extern __shared__ unsigned char smem_raw[];
    float4* reg4 = (float4*)(smem_raw + SM_REG4);   // [40*64]
    u64*    e_sm = (u64*)(smem_raw + SM_E);         // [4][432]
    u64*    hbuf = (u64*)(smem_raw + SM_H);         // [2][8][36]

    int t   = blockIdx.z;
    int ty0 = blockIdx.y * TY;
    int tx0 = blockIdx.x * TX;
    int tid = threadIdx.x;

    // stage region
    const float4* xp = g_xp + (size_t)t * XPH * XPW;
    #pragma unroll
    for (int i = tid; i < 40*64; i += 256) {
        int r = i >> 6, c = i & 63;
        reg4[i] = xp[(size_t)(ty0 + r) * XPW + tx0 + c];
    }
    __syncthreads();

    // register-cached query pixels for the e-plane (slots tid and tid+256)
    int er1 = tid / 36, ec1 = tid - er1 * 36;
    int it2 = tid + 256;
    int er2 = it2 / 36, ec2 = it2 - er2 * 36;       // valid when tid < 176
    float4 q1 = reg4[(er1 + 14) * 64 + (ec1 + 14)];
    float4 q2 = (tid < 176) ? reg4[(er2 + 14) * 64 + (ec2 + 14)] : make_float4(0.f,0.f,0.f,0.f);
    int nb1 = er1 * 64 + ec1;
    int nb2 = er2 * 64 + ec2;

    int ly = tid >> 5, l = tid & 31;

    unsigned keys[KSEL];
    #pragma unroll
    for (int i = 0; i < KSEL; i++) keys[i] = 0xFFFFFFFFu;

    // fill two f32x2 planes (4 offsets) from pre-decoded group word
    auto fillG = [&](u64* pA, u64* pB, uint4 gw) {
        int o0 = (int)(gw.x >> 16), o1 = (int)(gw.y >> 16);
        int o2 = (int)(gw.z >> 16), o3 = (int)(gw.w >> 16);
        {
            float4 n0 = reg4[nb1 + o0], n1 = reg4[nb1 + o1];
            float4 n2 = reg4[nb1 + o2], n3 = reg4[nb1 + o3];
            float a0 = q1.x-n0.x, b0 = q1.y-n0.y, c0 = q1.z-n0.z;
            float a1 = q1.x-n1.x, b1 = q1.y-n1.y, c1 = q1.z-n1.z;
            float a2 = q1.x-n2.x, b2 = q1.y-n2.y, c2 = q1.z-n2.z;
            float a3 = q1.x-n3.x, b3 = q1.y-n3.y, c3 = q1.z-n3.z;
            pA[tid] = packf2(a0*a0 + b0*b0 + c0*c0, a1*a1 + b1*b1 + c1*c1);
            pB[tid] = packf2(a2*a2 + b2*b2 + c2*c2, a3*a3 + b3*b3 + c3*c3);
        }
        if (tid < 176) {
            float4 n0 = reg4[nb2 + o0], n1 = reg4[nb2 + o1];
            float4 n2 = reg4[nb2 + o2], n3 = reg4[nb2 + o3];
            float a0 = q2.x-n0.x, b0 = q2.y-n0.y, c0 = q2.z-n0.z;
            float a1 = q2.x-n1.x, b1 = q2.y-n1.y, c1 = q2.z-n1.z;
            float a2 = q2.x-n2.x, b2 = q2.y-n2.y, c2 = q2.z-n2.z;
            float a3 = q2.x-n3.x, b3 = q2.y-n3.y, c3 = q2.z-n3.z;
            pA[it2] = packf2(a0*a0 + b0*b0 + c0*c0, a1*a1 + b1*b1 + c1*c1);
            pB[it2] = packf2(a2*a2 + b2*b2 + c2*c2, a3*a3 + b3*b3 + c3*c3);
        }
    };

    // single-key guarded insert (cheap VOTE; network only when some lane inserts)
    auto ins1 = [&](unsigned k) {
        if (__any_sync(0xffffffffu, k < keys[KSEL-1])) {
            #pragma unroll
            for (int s = KSEL-1; s >= 1; s--) keys[s] = umin(keys[s], umax(keys[s-1], k));
            keys[0] = umin(keys[0], k);
        }
    };

    // reduce 4 offsets (two independent chains) + top-K inserts
    auto bcG = [&](const u64* pA, const u64* pB, uint4 gw, bool kill123) {
        const u64* rA = pA + ly * 36;
        const u64* rB = pB + ly * 36;
        u64* hA = hbuf + (size_t)ly * 36;            // chain A buffers
        u64* hB = hbuf + (size_t)(8 + ly) * 36;      // chain B buffers
        u64 vaA = f2add(f2add(f2add(rA[l], rA[36+l]), f2add(rA[72+l], rA[108+l])), rA[144+l]);
        u64 vaB = f2add(f2add(f2add(rB[l], rB[36+l]), f2add(rB[72+l], rB[108+l])), rB[144+l]);
        hA[l] = vaA;
        hB[l] = vaB;
        if (l < 4) {   // spill columns 32..35: only 4 lanes do the work
            int c2 = 32 + l;
            u64 vbA = f2add(f2add(f2add(rA[c2], rA[36+c2]), f2add(rA[72+c2], rA[108+c2])), rA[144+c2]);
            u64 vbB = f2add(f2add(f2add(rB[c2], rB[36+c2]), f2add(rB[72+c2], rB[108+c2])), rB[144+c2]);
            hA[32 + l] = vbA;
            hB[32 + l] = vbB;
        }
        __syncwarp(0xffffffffu);
        u64 dA = f2add(f2add(f2add(hA[l], hA[l+1]), f2add(hA[l+2], hA[l+3])), hA[l+4]);
        u64 dB = f2add(f2add(f2add(hB[l], hB[l+1]), f2add(hB[l+2], hB[l+3])), hB[l+4]);
        unsigned k0 = ((unsigned)dA         & 0xFFFFFC00u) | (gw.x & 0x3FFu);
        unsigned k1 = ((unsigned)(dA >> 32) & 0xFFFFFC00u) | (gw.y & 0x3FFu);
        unsigned k2 = ((unsigned)dB         & 0xFFFFFC00u) | (gw.z & 0x3FFu);
        unsigned k3 = ((unsigned)(dB >> 32) & 0xFFFFFC00u) | (gw.w & 0x3FFu);
        if (kill123) { k1 = 0xFFFFFFFFu; k2 = 0xFFFFFFFFu; k3 = 0xFFFFFFFFu; }
        ins1(k0); ins1(k1); ins1(k2); ins1(k3);
    };

    const uint4* ordp = (const uint4*)g_ordw;
    auto loadg = [&](int g) -> uint4 {
        uint4 v = ordp[g];
        if (g == NGRP - 1) { v.y = v.x; v.z = v.x; v.w = v.x; }  // last group: 1 real offset
        return v;
    };

    uint4 w_cur = loadg(0);
    fillG(e_sm, e_sm + 432, w_cur);
    uint4 w_nxt = loadg(1);

    #pragma unroll 2
    for (int g = 0; g < NGRP; g++) {
        int side = g & 1;
        __syncthreads();
        if (g + 1 < NGRP) {
            u64* p2 = e_sm + (size_t)((side ^ 1) << 1) * 432;
            fillG(p2, p2 + 432, w_nxt);
        }
        uint4 w_n2 = (g + 2 < NGRP) ? loadg(g + 2) : make_uint4(0,0,0,0);
        u64* pc = e_sm + (size_t)(side << 1) * 432;
        bcG(pc, pc + 432, w_cur, g == NGRP - 1);
        w_cur = w_nxt; w_nxt = w_n2;
    }

    // --- softmax over (quantized) distances ---
    float w[KSEL];
    int   olin[KSEL];
    float beta = g_beta;
    float d0 = __uint_as_float(keys[0] & 0xFFFFFC00u);
    float ssum = 0.f;
    #pragma unroll
    for (int i = 0; i < KSEL; i++) {
        float di = __uint_as_float(keys[i] & 0xFFFFFC00u);
        float wi = expf(beta * (d0 - di));
        w[i] = wi; ssum += wi;
        int o  = (int)(keys[i] & 0x3FFu);
        int oyk = o / WSZ;
        int oxk = o - oyk * WSZ;
        olin[i] = oyk * 64 + oxk;
    }
    float inv = 1.0f / ssum;
    #pragma unroll
    for (int i = 0; i < KSEL; i++) w[i] *= inv;

    // --- weighted patch gather from smem region, plane-major write ---
    float* pd = g_pdeno + ((size_t)t * HH + (ty0 + ly)) * WW + (tx0 + l);
    int base_px = ly * 64 + l;
    #pragma unroll
    for (int dy = 0; dy < PSZ; dy++) {
        #pragma unroll
        for (int dx = 0; dx < PSZ; dx++) {
            float ax = 0.f, ay = 0.f, az = 0.f;
            int bb = base_px + dy * 64 + dx;
            #pragma unroll
            for (int k = 0; k < KSEL; k++) {
                float4 v = reg4[bb + olin[k]];
                ax += w[k] * v.x;
                ay += w[k] * v.y;
                az += w[k] * v.z;
            }
            int p = (dy * PSZ + dx) * 3;
            pd[(size_t)(p + 0) * PLANE] = ax;
            pd[(size_t)(p + 1) * PLANE] = ay;
            pd[(size_t)(p + 2) * PLANE] = az;
        }
    }
}

// ---------------- fold + denormalize ----------------
__global__ void k_fold(float* __restrict__ out) {
    int idx = blockIdx.x * 256 + threadIdx.x;        // over t*c*H*W
    if (idx >= TCNT*CH*HH*WW) return;
    int x = idx & 127;
    int r = idx >> 7;
    int y = r & 127;
    r >>= 7;
    int c = r % 3;
    int t = r / 3;
    float s = 0.f;
    int n = 0;
    #pragma unroll
    for (int py = 0; py < PSZ; py++) {
        int yy = y + 2 - py;
        if (yy < 0 || yy > HH-1) continue;
        #pragma unroll
        for (int px = 0; px < PSZ; px++) {
            int xx = x + 2 - px;
            if (xx < 0 || xx > WW-1) continue;
            int p = (py * PSZ + px) * 3 + c;
            s += g_pdeno[(size_t)p * PLANE + ((size_t)t * HH + yy) * WW + xx];
            n++;
        }
    }
    out[idx] = 127.5f * (s / (float)n + g_mean[t*3+c] + 1.0f);
}

// ---------------- launch ----------------
extern "C" void kernel_launch(void* const* d_in, const int* in_sizes, int n_in,
                              void* d_out, int out_size) {
    const float* noisy = (const float*)d_in[0];
    const int*   sigp  = (const int*)d_in[1];
    float*       out   = (float*)d_out;

    // host-side attribute setup (graph-capture safe; idempotent, deterministic)
    cudaFuncSetAttribute(k_main, cudaFuncAttributeMaxDynamicSharedMemorySize, SM_TOTAL);
    cudaFuncSetAttribute(k_main, cudaFuncAttributePreferredSharedMemoryCarveout,
                         cudaSharedmemCarveoutMaxShared);

    k_means<<<TCNT*CH, 256>>>(noisy, sigp);
    k_xp<<<(TCNT*XPH*XPW + 255)/256, 256>>>(noisy);
    k_ord<<<(NOFF + 255)/256, 256>>>();
    dim3 grid(WW/TX, HH/TY, TCNT);
    k_main<<<grid, 256, SM_TOTAL>>>();
    k_fold<<<(TCNT*CH*HH*WW + 255)/256, 256>>>(out);
}